// round 14
// baseline (speedup 1.0000x reference)
#include <cuda_runtime.h>
#include <cuda_bf16.h>

#define NQ        12
#define BLK       256
#define OUTDIM    256
#define HID       64
#define GB        16

typedef unsigned long long ull;

__device__ float g_z[4096 * NQ];   // scratch: z per batch element

__device__ __forceinline__ float2 cmul(float2 a, float2 b) {
    return make_float2(a.x * b.x - a.y * b.y, a.x * b.y + a.y * b.x);
}
__device__ __forceinline__ float2 cjf(float2 e, int c) {
    return c ? make_float2(e.x, -e.y) : e;
}

// ---- packed f32x2 helpers ----
__device__ __forceinline__ ull pk2(float lo, float hi) {
    ull r; asm("mov.b64 %0, {%1, %2};" : "=l"(r) : "f"(lo), "f"(hi)); return r;
}
__device__ __forceinline__ float2 unpk(ull v) {
    float lo, hi; asm("mov.b64 {%0, %1}, %2;" : "=f"(lo), "=f"(hi) : "l"(v));
    return make_float2(lo, hi);
}
__device__ __forceinline__ ull swp(ull v) {
    ull r;
    asm("{\n\t.reg .b32 lo, hi;\n\tmov.b64 {lo, hi}, %1;\n\tmov.b64 %0, {hi, lo};\n\t}"
        : "=l"(r) : "l"(v));
    return r;
}
__device__ __forceinline__ ull fma2p(ull a, ull b, ull c) {
    ull r; asm("fma.rn.f32x2 %0, %1, %2, %3;" : "=l"(r) : "l"(a), "l"(b), "l"(c));
    return r;
}
__device__ __forceinline__ ull mul2p(ull a, ull b) {
    ull r; asm("mul.rn.f32x2 %0, %1, %2;" : "=l"(r) : "l"(a), "l"(b)); return r;
}
__device__ __forceinline__ ull add2p(ull a, ull b) {
    ull r; asm("add.rn.f32x2 %0, %1, %2;" : "=l"(r) : "l"(a), "l"(b)); return r;
}

// real-rotation butterfly
__device__ __forceinline__ void bflyr(ull& a0, ull& a1, ull c2, ull s2, ull ns2) {
    ull n0 = fma2p(ns2, a1, mul2p(c2, a0));
    ull n1 = fma2p(c2,  a1, mul2p(s2, a0));
    a0 = n0; a1 = n1;
}

__host__ __device__ constexpr int Lmap(int b) {
    int r = 0;
    for (int p = 0; p <= 10; p++) {
        int par = 0;
        for (int q = p; q <= 11; q++) par ^= (b >> q) & 1;
        r |= par << p;
    }
    int par = 0;
    for (int q = 0; q <= 10; q++) par ^= (b >> q) & 1;
    return r | (par << 11);
}
__host__ __device__ constexpr int swzB(int x) { return x ^ (((x >> 4) & 7) << 1); }
struct PKt { int v[16]; };
__host__ __device__ constexpr PKt mkPK() {
    PKt t{};
    for (int k = 0; k < 16; k++) t.v[k] = swzB(Lmap(k << 8));
    return t;
}

__global__ __launch_bounds__(BLK, 4) void quantum_state_kernel(
    const float* __restrict__ x,    // [B, 48]
    const float* __restrict__ rw,   // [12, 3, 4]
    const float* __restrict__ rb)   // [12, 3]
{
    __shared__ __align__(16) float2 st[4096];
    __shared__ float2 sU10[NQ];
    __shared__ float  sCh[NQ];
    __shared__ float2 sEphi[NQ], sElam[NQ];
    __shared__ ull    sC2[NQ], sS2[NQ], sNS2[NQ];
    __shared__ float  zred[NQ][BLK/32];

    const int b    = blockIdx.x;
    const int tid  = threadIdx.x;
    const int lane = tid & 31;
    const int warp = tid >> 5;

    constexpr PKt PK = mkPK();

    if (tid < NQ) {
        const float* xb  = x  + b * 48 + tid * 4;
        const float* rwi = rw + tid * 12;
        const float* rbi = rb + tid * 3;
        float x0 = xb[0], x1 = xb[1], x2 = xb[2], x3 = xb[3];
        float th = rbi[0] + rwi[0]*x0 + rwi[1]*x1 + rwi[2] *x2 + rwi[3] *x3;
        float ph = rbi[1] + rwi[4]*x0 + rwi[5]*x1 + rwi[6] *x2 + rwi[7] *x3;
        float lm = rbi[2] + rwi[8]*x0 + rwi[9]*x1 + rwi[10]*x2 + rwi[11]*x3;
        float sh, ch, sp, cp, sl, cl;
        sincosf(th * 0.5f, &sh, &ch);
        sincosf(ph,        &sp, &cp);
        sincosf(lm,        &sl, &cl);
        sCh[tid]   = ch;
        sU10[tid]  = make_float2(cp * sh, sp * sh);
        sEphi[tid] = make_float2(cp, sp);
        sElam[tid] = make_float2(cl, sl);
        sC2[tid]   = pk2(ch, ch);
        sS2[tid]   = pk2(sh, sh);
        sNS2[tid]  = pk2(-sh, -sh);
    }
    __syncthreads();

    int y = tid; y ^= y >> 1; y ^= y >> 2; y ^= y >> 4;
    const int Ltid  = (y & 0xFF) | ((y & 1) << 11);
    const int PLtid = swzB(Ltid);
    const int t3    = tid & 7;
    const int tB    = tid ^ (((tid >> 4) & 7) << 1);
    const int cb    = ((tid >> 4) << 8) | (tid & 15);

    const int t0 = tid & 1, t1 = (tid >> 1) & 1, t2 = (tid >> 2) & 1,
              t3b = (tid >> 3) & 1, t4 = (tid >> 4) & 1, t5 = (tid >> 5) & 1,
              t6 = (tid >> 6) & 1, t7 = (tid >> 7) & 1;

    ull A[16];
    ull*        stu = (ull*)st;
    ulonglong2* st2 = (ulonglong2*)st;

    auto col0 = [&](int w, int bit) -> float2 {
        return bit ? sU10[w] : make_float2(sCh[w], 0.f);
    };

    // ===== build of (Lam1 ∘ perm ∘ layer-0-U3) state in mapping A =====
    {
        float2 base = col0(2, t5 ^ t6);
        base = cmul(base, col0(3, t4 ^ t5));
        base = cmul(base, col0(4, t3b ^ t4));
        base = cmul(base, col0(5, t2 ^ t3b));
        base = cmul(base, col0(6, t1 ^ t2));
        base = cmul(base, col0(7, t0 ^ t1));
        if (t7)  base = cmul(base, sElam[0]);
        if (t6)  base = cmul(base, sElam[1]);
        if (t5)  base = cmul(base, sElam[2]);
        if (t4)  base = cmul(base, sElam[3]);
        if (t3b) base = cmul(base, sElam[4]);
        if (t2)  base = cmul(base, sElam[5]);
        if (t1)  base = cmul(base, sElam[6]);
        if (t0)  base = cmul(base, sElam[7]);

        float2 baseG[2];
        #pragma unroll
        for (int k0 = 0; k0 < 2; k0++) {
            float2 g = cmul(col0(0, k0 ^ t7), col0(1, k0 ^ t6 ^ t7));
            baseG[k0] = cmul(base, g);
        }
        float2 bG4[4];
        bG4[0] = baseG[0];
        bG4[1] = cmul(baseG[1], sElam[11]);
        bG4[2] = cmul(baseG[0], sElam[10]);
        bG4[3] = cmul(bG4[1],   sElam[10]);

        float2 Qhi[4], Qlo[4];
        #pragma unroll
        for (int i = 0; i < 4; i++) {
            int m3 = i >> 1, m2 = i & 1;
            Qhi[i] = cmul(col0(8, m3 ^ t0), col0(9, m2));
            int m1 = i >> 1, m0 = i & 1;
            Qlo[i] = cmul(col0(10, m1), col0(11, m0));
        }
        Qhi[1] = cmul(Qhi[1], sElam[9]);
        Qhi[2] = cmul(Qhi[2], cmul(sElam[8], sElam[9]));
        Qhi[3] = cmul(Qhi[3], sElam[8]);

        #pragma unroll
        for (int k = 0; k < 16; k++) {
            const int k0 = k & 1, k1 = (k >> 1) & 1, k2 = (k >> 2) & 1, k3 = k >> 3;
            const int m3 = k3, m2 = k2 ^ k3, m1 = k1 ^ k2, m0 = k0 ^ k1;
            float2 v = cmul(bG4[k & 3], cmul(Qhi[(m3 << 1) | m2], Qlo[(m1 << 1) | m0]));
            A[k] = pk2(v.x, v.y);
        }
    }

    // ===== layers 1,2 — all gates register-local via A/C/B mappings =====
    #pragma unroll
    for (int layer = 1; layer < 3; layer++) {
        #pragma unroll
        for (int w = 8; w < 12; w++) {
            const int bp = 11 - w;
            const ull c2 = sC2[w], s2 = sS2[w], ns2 = sNS2[w];
            #pragma unroll
            for (int k0 = 0; k0 < 16; k0++) {
                if (k0 & (1 << bp)) continue;
                const int k1 = k0 | (1 << bp);
                bflyr(A[k0], A[k1], c2, s2, ns2);
            }
        }

        __syncthreads();
        #pragma unroll
        for (int p = 0; p < 8; p++)
            st2[(tid << 3) | (p ^ t3)] = make_ulonglong2(A[2*p], A[2*p+1]);
        __syncthreads();
        #pragma unroll
        for (int k = 0; k < 16; k++)
            A[k] = stu[cb ^ ((k << 4) | ((k & 7) << 1))];

        #pragma unroll
        for (int w = 4; w < 8; w++) {
            const int bp = 7 - w;
            const ull c2 = sC2[w], s2 = sS2[w], ns2 = sNS2[w];
            #pragma unroll
            for (int k0 = 0; k0 < 16; k0++) {
                if (k0 & (1 << bp)) continue;
                const int k1 = k0 | (1 << bp);
                bflyr(A[k0], A[k1], c2, s2, ns2);
            }
        }

        __syncthreads();
        #pragma unroll
        for (int k = 0; k < 16; k++)
            stu[cb ^ ((k << 4) | ((k & 7) << 1))] = A[k];
        __syncthreads();
        #pragma unroll
        for (int k = 0; k < 16; k++)
            A[k] = stu[(k << 8) | tB];

        #pragma unroll
        for (int w = 0; w < 4; w++) {
            const int bp = 3 - w;
            const ull c2 = sC2[w], s2 = sS2[w], ns2 = sNS2[w];
            #pragma unroll
            for (int k0 = 0; k0 < 16; k0++) {
                if (k0 & (1 << bp)) continue;
                const int k1 = k0 | (1 << bp);
                bflyr(A[k0], A[k1], c2, s2, ns2);
            }
        }

        if (layer == 1) {
            __syncthreads();
            #pragma unroll
            for (int k = 0; k < 16; k++)
                stu[PLtid ^ PK.v[k]] = A[k];
            __syncthreads();
            #pragma unroll
            for (int p = 0; p < 8; p++) {
                ulonglong2 v = st2[(tid << 3) | (p ^ t3)];
                A[2*p]   = v.x;
                A[2*p+1] = v.y;
            }

            // G = (Phi1 relabeled by L^{-1}) * Lam2
            float2 T01g[4], T23v0[4], T23v1[4];
            {
                float2 gt = make_float2(1.f, 0.f);
                if (t5 ^ t6)  gt = cmul(gt, sEphi[2]);
                if (t4 ^ t5)  gt = cmul(gt, sEphi[3]);
                if (t3b ^ t4) gt = cmul(gt, sEphi[4]);
                if (t2 ^ t3b) gt = cmul(gt, sEphi[5]);
                if (t1 ^ t2)  gt = cmul(gt, sEphi[6]);
                if (t0 ^ t1)  gt = cmul(gt, sEphi[7]);
                if (t7)  gt = cmul(gt, sElam[0]);
                if (t6)  gt = cmul(gt, sElam[1]);
                if (t5)  gt = cmul(gt, sElam[2]);
                if (t4)  gt = cmul(gt, sElam[3]);
                if (t3b) gt = cmul(gt, sElam[4]);
                if (t2)  gt = cmul(gt, sElam[5]);
                if (t1)  gt = cmul(gt, sElam[6]);
                if (t0)  gt = cmul(gt, sElam[7]);
                if (t7)       gt = cmul(gt, sEphi[0]);
                if (t6 ^ t7)  gt = cmul(gt, sEphi[1]);
                if (t0)       gt = cmul(gt, sEphi[8]);

                float2 E0 = cmul(sElam[11], cmul(cjf(sEphi[0], t7), cjf(sEphi[1], t6 ^ t7)));
                float2 E1 = sElam[10];
                float2 E2 = sElam[9];
                float2 E3 = cmul(sElam[8], cjf(sEphi[8], t0));
                float2 X01 = sEphi[11], X12 = sEphi[10], X23 = sEphi[9];

                T01g[0] = gt;
                T01g[1] = cmul(gt, cmul(E0, X01));
                T01g[2] = cmul(gt, cmul(E1, X01));
                T01g[3] = cmul(gt, cmul(E0, E1));

                float2 e2x = cmul(E2, X23);
                float2 e3x = cmul(E3, X23);
                float2 e23 = cmul(E2, E3);
                T23v0[0] = make_float2(1.f, 0.f);
                T23v0[1] = cmul(e2x, X12);
                T23v0[2] = e3x;
                T23v0[3] = cmul(e23, X12);
                T23v1[0] = X12;
                T23v1[1] = e2x;
                T23v1[2] = cmul(e3x, X12);
                T23v1[3] = e23;
            }
            #pragma unroll
            for (int k = 0; k < 16; k++) {
                float2 g = cmul(T01g[k & 3],
                                ((k >> 1) & 1) ? T23v1[k >> 2] : T23v0[k >> 2]);
                ull gx2  = pk2(g.x, g.x);
                ull gyn2 = pk2(-g.y, g.y);
                A[k] = fma2p(gx2, A[k], mul2p(gyn2, swp(A[k])));
            }
        }
    }

    // ===== Z expectations in mapping B =====
    float SA = 0.f, SB = 0.f, SC = 0.f, SD = 0.f;
    #pragma unroll
    for (int k = 0; k < 16; k++) {
        float2 v = unpk(A[k]);
        float pr = v.x * v.x + v.y * v.y;
        const int k0 = k & 1, k1 = (k >> 1) & 1, k2 = (k >> 2) & 1, k3 = k >> 3;
        SA += (k0 ^ k1 ^ k2)      ? -pr : pr;
        SB += (k2 ^ k3)           ? -pr : pr;
        SC += (k1 ^ k2 ^ k3)      ? -pr : pr;
        SD += (k0 ^ k1 ^ k2 ^ k3) ? -pr : pr;
    }
    float zl[NQ];
    {
        const int ptid = __popc(tid) & 1;
        zl[0] = ptid ? -SA : SA;
        zl[1] = SB;
        zl[2] = SC;
        zl[3] = SD;
        #pragma unroll
        for (int w = 4; w < 12; w++) {
            const int j = 11 - w;
            zl[w] = (__popc(tid >> j) & 1) ? -SD : SD;
        }
    }

    {
        ull zp[6];
        #pragma unroll
        for (int i = 0; i < 6; i++) zp[i] = pk2(zl[i], zl[i + 6]);
        #pragma unroll
        for (int off = 16; off > 0; off >>= 1) {
            #pragma unroll
            for (int i = 0; i < 6; i++)
                zp[i] = add2p(zp[i], __shfl_xor_sync(0xFFFFFFFFu, zp[i], off));
        }
        if (lane == 0) {
            #pragma unroll
            for (int i = 0; i < 6; i++) {
                float2 v = unpk(zp[i]);
                zred[i][warp]     = v.x;
                zred[i + 6][warp] = v.y;
            }
        }
    }
    __syncthreads();
    if (tid < NQ) {
        float z = 0.f;
        #pragma unroll
        for (int j = 0; j < BLK / 32; j++) z += zred[tid][j];
        g_z[b * NQ + tid] = z;
    }
}

// ===== MLP tail kernel: 16 batch elements per CTA, thread = output column =====
__global__ __launch_bounds__(256) void mlp_tail_kernel(
    const float* __restrict__ w1,   // [64, 12]
    const float* __restrict__ b1,   // [64]
    const float* __restrict__ w2,   // [256, 64]
    const float* __restrict__ b2,   // [256]
    float* __restrict__ out)        // [B, 256]
{
    __shared__ float w1s[HID * NQ];
    __shared__ float b1s[HID];
    __shared__ float zs[GB * NQ];
    __shared__ __align__(16) float hs[GB][HID];

    const int tid = threadIdx.x;
    const int b0  = blockIdx.x * GB;

    for (int i = tid; i < HID * NQ; i += 256) w1s[i] = w1[i];
    if (tid < HID) b1s[tid] = b1[tid];
    for (int i = tid; i < GB * NQ; i += 256) zs[i] = g_z[b0 * NQ + i];
    __syncthreads();

    // MLP1: GB*HID = 1024 h values, 4 per thread
    #pragma unroll
    for (int r = 0; r < GB * HID / 256; r++) {
        const int idx = tid + r * 256;
        const int bb = idx >> 6, j = idx & 63;
        float h = b1s[j];
        #pragma unroll
        for (int i = 0; i < NQ; i++) h += zs[bb * NQ + i] * w1s[j * NQ + i];
        hs[bb][j] = fmaxf(h, 0.f);
    }
    __syncthreads();

    // MLP2: thread owns output column o = tid; w2 row register-cached in halves
    const int o = tid;
    float acc[GB];
    #pragma unroll
    for (int bb = 0; bb < GB; bb++) acc[bb] = 0.f;
    #pragma unroll
    for (int jh = 0; jh < 2; jh++) {
        float4 wr[8];
        #pragma unroll
        for (int q = 0; q < 8; q++)
            wr[q] = *(const float4*)(w2 + o * HID + jh * 32 + q * 4);
        #pragma unroll
        for (int bb = 0; bb < GB; bb++) {
            const float4* hp = (const float4*)(&hs[bb][jh * 32]);
            float s = 0.f;
            #pragma unroll
            for (int q = 0; q < 8; q++) {
                float4 h4 = hp[q];
                s += wr[q].x * h4.x + wr[q].y * h4.y + wr[q].z * h4.z + wr[q].w * h4.w;
            }
            acc[bb] += s;
        }
    }
    const float bias = b2[o];
    #pragma unroll
    for (int bb = 0; bb < GB; bb++)
        out[(b0 + bb) * OUTDIM + o] = acc[bb] + bias;
}

extern "C" void kernel_launch(void* const* d_in, const int* in_sizes, int n_in,
                              void* d_out, int out_size) {
    const float* x  = (const float*)d_in[0];
    const float* rw = (const float*)d_in[1];
    const float* rb = (const float*)d_in[2];
    const float* w1 = (const float*)d_in[3];
    const float* b1 = (const float*)d_in[4];
    const float* w2 = (const float*)d_in[5];
    const float* b2 = (const float*)d_in[6];
    float* out = (float*)d_out;
    int batch = in_sizes[0] / 48;
    quantum_state_kernel<<<batch, BLK>>>(x, rw, rb);
    mlp_tail_kernel<<<batch / GB, 256>>>(w1, b1, w2, b2, out);
}

// round 15
// speedup vs baseline: 1.0398x; 1.0398x over previous
#include <cuda_runtime.h>
#include <cuda_bf16.h>

#define NQ        12
#define BLK       256
#define OUTDIM    256
#define HID       64
#define GB        8

typedef unsigned long long ull;

__device__ float g_z[4096 * NQ];   // scratch: z per batch element

__device__ __forceinline__ float2 cmul(float2 a, float2 b) {
    return make_float2(a.x * b.x - a.y * b.y, a.x * b.y + a.y * b.x);
}
__device__ __forceinline__ float2 cjf(float2 e, int c) {
    return c ? make_float2(e.x, -e.y) : e;
}

// ---- packed f32x2 helpers ----
__device__ __forceinline__ ull pk2(float lo, float hi) {
    ull r; asm("mov.b64 %0, {%1, %2};" : "=l"(r) : "f"(lo), "f"(hi)); return r;
}
__device__ __forceinline__ float2 unpk(ull v) {
    float lo, hi; asm("mov.b64 {%0, %1}, %2;" : "=f"(lo), "=f"(hi) : "l"(v));
    return make_float2(lo, hi);
}
__device__ __forceinline__ ull swp(ull v) {
    ull r;
    asm("{\n\t.reg .b32 lo, hi;\n\tmov.b64 {lo, hi}, %1;\n\tmov.b64 %0, {hi, lo};\n\t}"
        : "=l"(r) : "l"(v));
    return r;
}
__device__ __forceinline__ ull fma2p(ull a, ull b, ull c) {
    ull r; asm("fma.rn.f32x2 %0, %1, %2, %3;" : "=l"(r) : "l"(a), "l"(b), "l"(c));
    return r;
}
__device__ __forceinline__ ull mul2p(ull a, ull b) {
    ull r; asm("mul.rn.f32x2 %0, %1, %2;" : "=l"(r) : "l"(a), "l"(b)); return r;
}
__device__ __forceinline__ ull add2p(ull a, ull b) {
    ull r; asm("add.rn.f32x2 %0, %1, %2;" : "=l"(r) : "l"(a), "l"(b)); return r;
}

// real-rotation butterfly
__device__ __forceinline__ void bflyr(ull& a0, ull& a1, ull c2, ull s2, ull ns2) {
    ull n0 = fma2p(ns2, a1, mul2p(c2, a0));
    ull n1 = fma2p(c2,  a1, mul2p(s2, a0));
    a0 = n0; a1 = n1;
}

__host__ __device__ constexpr int Lmap(int b) {
    int r = 0;
    for (int p = 0; p <= 10; p++) {
        int par = 0;
        for (int q = p; q <= 11; q++) par ^= (b >> q) & 1;
        r |= par << p;
    }
    int par = 0;
    for (int q = 0; q <= 10; q++) par ^= (b >> q) & 1;
    return r | (par << 11);
}
__host__ __device__ constexpr int swzB(int x) { return x ^ (((x >> 4) & 7) << 1); }
struct PKt { int v[16]; };
__host__ __device__ constexpr PKt mkPK() {
    PKt t{};
    for (int k = 0; k < 16; k++) t.v[k] = swzB(Lmap(k << 8));
    return t;
}

__global__ __launch_bounds__(BLK, 4) void quantum_state_kernel(
    const float* __restrict__ x,    // [B, 48]
    const float* __restrict__ rw,   // [12, 3, 4]
    const float* __restrict__ rb)   // [12, 3]
{
    __shared__ __align__(16) float2 st[4096];
    __shared__ float2 sU10[NQ];
    __shared__ float  sCh[NQ];
    __shared__ float2 sEphi[NQ], sElam[NQ];
    __shared__ ull    sC2[NQ], sS2[NQ], sNS2[NQ];
    __shared__ float  zred[NQ][BLK/32];

    const int b    = blockIdx.x;
    const int tid  = threadIdx.x;
    const int lane = tid & 31;
    const int warp = tid >> 5;

    constexpr PKt PK = mkPK();

    if (tid < NQ) {
        const float* xb  = x  + b * 48 + tid * 4;
        const float* rwi = rw + tid * 12;
        const float* rbi = rb + tid * 3;
        float x0 = xb[0], x1 = xb[1], x2 = xb[2], x3 = xb[3];
        float th = rbi[0] + rwi[0]*x0 + rwi[1]*x1 + rwi[2] *x2 + rwi[3] *x3;
        float ph = rbi[1] + rwi[4]*x0 + rwi[5]*x1 + rwi[6] *x2 + rwi[7] *x3;
        float lm = rbi[2] + rwi[8]*x0 + rwi[9]*x1 + rwi[10]*x2 + rwi[11]*x3;
        float sh, ch, sp, cp, sl, cl;
        sincosf(th * 0.5f, &sh, &ch);
        sincosf(ph,        &sp, &cp);
        sincosf(lm,        &sl, &cl);
        sCh[tid]   = ch;
        sU10[tid]  = make_float2(cp * sh, sp * sh);
        sEphi[tid] = make_float2(cp, sp);
        sElam[tid] = make_float2(cl, sl);
        sC2[tid]   = pk2(ch, ch);
        sS2[tid]   = pk2(sh, sh);
        sNS2[tid]  = pk2(-sh, -sh);
    }
    __syncthreads();

    int y = tid; y ^= y >> 1; y ^= y >> 2; y ^= y >> 4;
    const int Ltid  = (y & 0xFF) | ((y & 1) << 11);
    const int PLtid = swzB(Ltid);
    const int t3    = tid & 7;
    const int tB    = tid ^ (((tid >> 4) & 7) << 1);
    const int cb    = ((tid >> 4) << 8) | (tid & 15);

    const int t0 = tid & 1, t1 = (tid >> 1) & 1, t2 = (tid >> 2) & 1,
              t3b = (tid >> 3) & 1, t4 = (tid >> 4) & 1, t5 = (tid >> 5) & 1,
              t6 = (tid >> 6) & 1, t7 = (tid >> 7) & 1;

    ull A[16];
    ull*        stu = (ull*)st;
    ulonglong2* st2 = (ulonglong2*)st;

    auto col0 = [&](int w, int bit) -> float2 {
        return bit ? sU10[w] : make_float2(sCh[w], 0.f);
    };

    // ===== build of (Lam1 ∘ perm ∘ layer-0-U3) state in mapping A =====
    {
        float2 base = col0(2, t5 ^ t6);
        base = cmul(base, col0(3, t4 ^ t5));
        base = cmul(base, col0(4, t3b ^ t4));
        base = cmul(base, col0(5, t2 ^ t3b));
        base = cmul(base, col0(6, t1 ^ t2));
        base = cmul(base, col0(7, t0 ^ t1));
        if (t7)  base = cmul(base, sElam[0]);
        if (t6)  base = cmul(base, sElam[1]);
        if (t5)  base = cmul(base, sElam[2]);
        if (t4)  base = cmul(base, sElam[3]);
        if (t3b) base = cmul(base, sElam[4]);
        if (t2)  base = cmul(base, sElam[5]);
        if (t1)  base = cmul(base, sElam[6]);
        if (t0)  base = cmul(base, sElam[7]);

        float2 baseG[2];
        #pragma unroll
        for (int k0 = 0; k0 < 2; k0++) {
            float2 g = cmul(col0(0, k0 ^ t7), col0(1, k0 ^ t6 ^ t7));
            baseG[k0] = cmul(base, g);
        }
        float2 bG4[4];
        bG4[0] = baseG[0];
        bG4[1] = cmul(baseG[1], sElam[11]);
        bG4[2] = cmul(baseG[0], sElam[10]);
        bG4[3] = cmul(bG4[1],   sElam[10]);

        float2 Qhi[4], Qlo[4];
        #pragma unroll
        for (int i = 0; i < 4; i++) {
            int m3 = i >> 1, m2 = i & 1;
            Qhi[i] = cmul(col0(8, m3 ^ t0), col0(9, m2));
            int m1 = i >> 1, m0 = i & 1;
            Qlo[i] = cmul(col0(10, m1), col0(11, m0));
        }
        Qhi[1] = cmul(Qhi[1], sElam[9]);
        Qhi[2] = cmul(Qhi[2], cmul(sElam[8], sElam[9]));
        Qhi[3] = cmul(Qhi[3], sElam[8]);

        #pragma unroll
        for (int k = 0; k < 16; k++) {
            const int k0 = k & 1, k1 = (k >> 1) & 1, k2 = (k >> 2) & 1, k3 = k >> 3;
            const int m3 = k3, m2 = k2 ^ k3, m1 = k1 ^ k2, m0 = k0 ^ k1;
            float2 v = cmul(bG4[k & 3], cmul(Qhi[(m3 << 1) | m2], Qlo[(m1 << 1) | m0]));
            A[k] = pk2(v.x, v.y);
        }
    }

    // ===== layers 1,2 — all gates register-local via A/C/B mappings =====
    #pragma unroll
    for (int layer = 1; layer < 3; layer++) {
        #pragma unroll
        for (int w = 8; w < 12; w++) {
            const int bp = 11 - w;
            const ull c2 = sC2[w], s2 = sS2[w], ns2 = sNS2[w];
            #pragma unroll
            for (int k0 = 0; k0 < 16; k0++) {
                if (k0 & (1 << bp)) continue;
                const int k1 = k0 | (1 << bp);
                bflyr(A[k0], A[k1], c2, s2, ns2);
            }
        }

        __syncthreads();
        #pragma unroll
        for (int p = 0; p < 8; p++)
            st2[(tid << 3) | (p ^ t3)] = make_ulonglong2(A[2*p], A[2*p+1]);
        __syncthreads();
        #pragma unroll
        for (int k = 0; k < 16; k++)
            A[k] = stu[cb ^ ((k << 4) | ((k & 7) << 1))];

        #pragma unroll
        for (int w = 4; w < 8; w++) {
            const int bp = 7 - w;
            const ull c2 = sC2[w], s2 = sS2[w], ns2 = sNS2[w];
            #pragma unroll
            for (int k0 = 0; k0 < 16; k0++) {
                if (k0 & (1 << bp)) continue;
                const int k1 = k0 | (1 << bp);
                bflyr(A[k0], A[k1], c2, s2, ns2);
            }
        }

        __syncthreads();
        #pragma unroll
        for (int k = 0; k < 16; k++)
            stu[cb ^ ((k << 4) | ((k & 7) << 1))] = A[k];
        __syncthreads();
        #pragma unroll
        for (int k = 0; k < 16; k++)
            A[k] = stu[(k << 8) | tB];

        #pragma unroll
        for (int w = 0; w < 4; w++) {
            const int bp = 3 - w;
            const ull c2 = sC2[w], s2 = sS2[w], ns2 = sNS2[w];
            #pragma unroll
            for (int k0 = 0; k0 < 16; k0++) {
                if (k0 & (1 << bp)) continue;
                const int k1 = k0 | (1 << bp);
                bflyr(A[k0], A[k1], c2, s2, ns2);
            }
        }

        if (layer == 1) {
            __syncthreads();
            #pragma unroll
            for (int k = 0; k < 16; k++)
                stu[PLtid ^ PK.v[k]] = A[k];
            __syncthreads();
            #pragma unroll
            for (int p = 0; p < 8; p++) {
                ulonglong2 v = st2[(tid << 3) | (p ^ t3)];
                A[2*p]   = v.x;
                A[2*p+1] = v.y;
            }

            // G = (Phi1 relabeled by L^{-1}) * Lam2
            float2 T01g[4], T23v0[4], T23v1[4];
            {
                float2 gt = make_float2(1.f, 0.f);
                if (t5 ^ t6)  gt = cmul(gt, sEphi[2]);
                if (t4 ^ t5)  gt = cmul(gt, sEphi[3]);
                if (t3b ^ t4) gt = cmul(gt, sEphi[4]);
                if (t2 ^ t3b) gt = cmul(gt, sEphi[5]);
                if (t1 ^ t2)  gt = cmul(gt, sEphi[6]);
                if (t0 ^ t1)  gt = cmul(gt, sEphi[7]);
                if (t7)  gt = cmul(gt, sElam[0]);
                if (t6)  gt = cmul(gt, sElam[1]);
                if (t5)  gt = cmul(gt, sElam[2]);
                if (t4)  gt = cmul(gt, sElam[3]);
                if (t3b) gt = cmul(gt, sElam[4]);
                if (t2)  gt = cmul(gt, sElam[5]);
                if (t1)  gt = cmul(gt, sElam[6]);
                if (t0)  gt = cmul(gt, sElam[7]);
                if (t7)       gt = cmul(gt, sEphi[0]);
                if (t6 ^ t7)  gt = cmul(gt, sEphi[1]);
                if (t0)       gt = cmul(gt, sEphi[8]);

                float2 E0 = cmul(sElam[11], cmul(cjf(sEphi[0], t7), cjf(sEphi[1], t6 ^ t7)));
                float2 E1 = sElam[10];
                float2 E2 = sElam[9];
                float2 E3 = cmul(sElam[8], cjf(sEphi[8], t0));
                float2 X01 = sEphi[11], X12 = sEphi[10], X23 = sEphi[9];

                T01g[0] = gt;
                T01g[1] = cmul(gt, cmul(E0, X01));
                T01g[2] = cmul(gt, cmul(E1, X01));
                T01g[3] = cmul(gt, cmul(E0, E1));

                float2 e2x = cmul(E2, X23);
                float2 e3x = cmul(E3, X23);
                float2 e23 = cmul(E2, E3);
                T23v0[0] = make_float2(1.f, 0.f);
                T23v0[1] = cmul(e2x, X12);
                T23v0[2] = e3x;
                T23v0[3] = cmul(e23, X12);
                T23v1[0] = X12;
                T23v1[1] = e2x;
                T23v1[2] = cmul(e3x, X12);
                T23v1[3] = e23;
            }
            #pragma unroll
            for (int k = 0; k < 16; k++) {
                float2 g = cmul(T01g[k & 3],
                                ((k >> 1) & 1) ? T23v1[k >> 2] : T23v0[k >> 2]);
                ull gx2  = pk2(g.x, g.x);
                ull gyn2 = pk2(-g.y, g.y);
                A[k] = fma2p(gx2, A[k], mul2p(gyn2, swp(A[k])));
            }
        }
    }

    // ===== Z expectations in mapping B =====
    float SA = 0.f, SB = 0.f, SC = 0.f, SD = 0.f;
    #pragma unroll
    for (int k = 0; k < 16; k++) {
        float2 v = unpk(A[k]);
        float pr = v.x * v.x + v.y * v.y;
        const int k0 = k & 1, k1 = (k >> 1) & 1, k2 = (k >> 2) & 1, k3 = k >> 3;
        SA += (k0 ^ k1 ^ k2)      ? -pr : pr;
        SB += (k2 ^ k3)           ? -pr : pr;
        SC += (k1 ^ k2 ^ k3)      ? -pr : pr;
        SD += (k0 ^ k1 ^ k2 ^ k3) ? -pr : pr;
    }
    float zl[NQ];
    {
        const int ptid = __popc(tid) & 1;
        zl[0] = ptid ? -SA : SA;
        zl[1] = SB;
        zl[2] = SC;
        zl[3] = SD;
        #pragma unroll
        for (int w = 4; w < 12; w++) {
            const int j = 11 - w;
            zl[w] = (__popc(tid >> j) & 1) ? -SD : SD;
        }
    }

    {
        ull zp[6];
        #pragma unroll
        for (int i = 0; i < 6; i++) zp[i] = pk2(zl[i], zl[i + 6]);
        #pragma unroll
        for (int off = 16; off > 0; off >>= 1) {
            #pragma unroll
            for (int i = 0; i < 6; i++)
                zp[i] = add2p(zp[i], __shfl_xor_sync(0xFFFFFFFFu, zp[i], off));
        }
        if (lane == 0) {
            #pragma unroll
            for (int i = 0; i < 6; i++) {
                float2 v = unpk(zp[i]);
                zred[i][warp]     = v.x;
                zred[i + 6][warp] = v.y;
            }
        }
    }
    __syncthreads();
    if (tid < NQ) {
        float z = 0.f;
        #pragma unroll
        for (int j = 0; j < BLK / 32; j++) z += zred[tid][j];
        g_z[b * NQ + tid] = z;
    }
}

// ===== MLP tail v2: GB elems/CTA, w2 transposed in dynamic smem =====
// dyn smem layout (floats): w2T[64*257] | hs[GB*64] | w1s[64*13] | zs[GB*12] | b1s[64]
#define W2T_N   (64 * 257)
#define HS_OFF  (W2T_N)
#define W1_OFF  (HS_OFF + GB * HID)
#define ZS_OFF  (W1_OFF + 64 * 13)
#define B1_OFF  (ZS_OFF + GB * NQ)
#define SMEM_FLOATS (B1_OFF + 64)

__global__ __launch_bounds__(256) void mlp_tail_kernel(
    const float* __restrict__ w1,   // [64, 12]
    const float* __restrict__ b1,   // [64]
    const float* __restrict__ w2,   // [256, 64]
    const float* __restrict__ b2,   // [256]
    float* __restrict__ out)        // [B, 256]
{
    extern __shared__ __align__(16) float sm[];
    float* w2T = sm;
    float* hs  = sm + HS_OFF;
    float* w1s = sm + W1_OFF;
    float* zs  = sm + ZS_OFF;
    float* b1s = sm + B1_OFF;

    const int tid = threadIdx.x;
    const int b0  = blockIdx.x * GB;

    // coalesced load + transpose of w2 into padded smem
    {
        const float4* w2v = (const float4*)w2;
        #pragma unroll
        for (int r = 0; r < 16; r++) {
            const int i4 = r * 256 + tid;       // float4 index in [0,4096)
            float4 v = w2v[i4];
            const int o = i4 >> 4;              // row (output column index)
            const int j = (i4 & 15) << 2;       // col within row
            w2T[(j + 0) * 257 + o] = v.x;
            w2T[(j + 1) * 257 + o] = v.y;
            w2T[(j + 2) * 257 + o] = v.z;
            w2T[(j + 3) * 257 + o] = v.w;
        }
    }
    // w1 (padded stride 13), b1, z
    for (int i = tid; i < HID * NQ; i += 256)
        w1s[(i / NQ) * 13 + (i % NQ)] = w1[i];
    if (tid < HID) b1s[tid] = b1[tid];
    for (int i = tid; i < GB * NQ; i += 256) zs[i] = g_z[b0 * NQ + i];
    __syncthreads();

    // MLP1: GB*HID h values, (GB*64/256) per thread
    #pragma unroll
    for (int r = 0; r < GB * HID / 256; r++) {
        const int idx = tid + r * 256;
        const int bb = idx >> 6, j = idx & 63;
        float h = b1s[j];
        #pragma unroll
        for (int i = 0; i < NQ; i++) h += zs[bb * NQ + i] * w1s[j * 13 + i];
        hs[bb * HID + j] = fmaxf(h, 0.f);
    }
    __syncthreads();

    // MLP2: thread owns output column o = tid
    const int o = tid;
    float acc[GB];
    #pragma unroll
    for (int bb = 0; bb < GB; bb++) acc[bb] = 0.f;
    #pragma unroll
    for (int jq = 0; jq < 16; jq++) {
        const float wa = w2T[(4*jq + 0) * 257 + o];
        const float wb = w2T[(4*jq + 1) * 257 + o];
        const float wc = w2T[(4*jq + 2) * 257 + o];
        const float wd = w2T[(4*jq + 3) * 257 + o];
        #pragma unroll
        for (int bb = 0; bb < GB; bb++) {
            const float4 h4 = *(const float4*)(&hs[bb * HID + 4*jq]);
            acc[bb] += wa * h4.x + wb * h4.y + wc * h4.z + wd * h4.w;
        }
    }
    const float bias = b2[o];
    #pragma unroll
    for (int bb = 0; bb < GB; bb++)
        out[(b0 + bb) * OUTDIM + o] = acc[bb] + bias;
}

extern "C" void kernel_launch(void* const* d_in, const int* in_sizes, int n_in,
                              void* d_out, int out_size) {
    const float* x  = (const float*)d_in[0];
    const float* rw = (const float*)d_in[1];
    const float* rb = (const float*)d_in[2];
    const float* w1 = (const float*)d_in[3];
    const float* b1 = (const float*)d_in[4];
    const float* w2 = (const float*)d_in[5];
    const float* b2 = (const float*)d_in[6];
    float* out = (float*)d_out;
    int batch = in_sizes[0] / 48;

    static int smem_set = 0;
    if (!smem_set) {
        cudaFuncSetAttribute(mlp_tail_kernel,
                             cudaFuncAttributeMaxDynamicSharedMemorySize,
                             SMEM_FLOATS * (int)sizeof(float));
        smem_set = 1;
    }
    quantum_state_kernel<<<batch, BLK>>>(x, rw, rb);
    mlp_tail_kernel<<<batch / GB, 256, SMEM_FLOATS * sizeof(float)>>>(w1, b1, w2, b2, out);
}